// round 11
// baseline (speedup 1.0000x reference)
#include <cuda_runtime.h>
#include <cuda_fp16.h>
#include <cstdint>

// Problem dims
#define Bz 4096
#define Iz 256
#define Oz 256
#define Kz 8192   // 2 * Iz * 16 ; k = s*4096 + i*16 + g

// Scratch globals (no allocs allowed)
__device__ float4 g_P[(size_t)Bz * Iz];        // per-(b,i) exp table (16 MB)
__device__ __half g_W[(size_t)Oz * Kz];        // weights fp16 (4 MB)
__device__ float  g_part[2][(size_t)Bz * Oz];  // split-K partials (8 MB)

// ---------------------------------------------------------------- helpers --
__device__ __forceinline__ uint32_t smem_u32(const void* p) {
    uint32_t a;
    asm("{ .reg .u64 t; cvta.to.shared.u64 t, %1; cvt.u32.u64 %0, t; }"
        : "=r"(a) : "l"(p));
    return a;
}
__device__ __forceinline__ void cp16(uint32_t dst, const void* src) {
    asm volatile("cp.async.cg.shared.global [%0], [%1], 16;" :: "r"(dst), "l"(src) : "memory");
}
__device__ __forceinline__ void cp_commit() {
    asm volatile("cp.async.commit_group;" ::: "memory");
}
__device__ __forceinline__ void cp_wait2() {
    asm volatile("cp.async.wait_group 2;" ::: "memory");
}
__device__ __forceinline__ void ldsm4(uint32_t* r, uint32_t a) {
    asm volatile("ldmatrix.sync.aligned.m8n8.x4.shared.b16 {%0,%1,%2,%3}, [%4];"
                 : "=r"(r[0]), "=r"(r[1]), "=r"(r[2]), "=r"(r[3]) : "r"(a));
}
__device__ __forceinline__ void mma16816(float* d, const uint32_t* a, const uint32_t* b) {
    asm volatile(
        "mma.sync.aligned.m16n8k16.row.col.f32.f16.f16.f32 "
        "{%0,%1,%2,%3}, {%4,%5,%6,%7}, {%8,%9}, {%0,%1,%2,%3};"
        : "+f"(d[0]), "+f"(d[1]), "+f"(d[2]), "+f"(d[3])
        : "r"(a[0]), "r"(a[1]), "r"(a[2]), "r"(a[3]), "r"(b[0]), "r"(b[1]));
}
__device__ __forceinline__ uint32_t packh(__half a, __half b) {
    return ((uint32_t)__half_as_ushort(b) << 16) | __half_as_ushort(a);
}

// ------------------------------------------------------- merged pre-pass --
// blocks [0,4096): P table {e^-.1x, e^-.06x, e^+.1x, e^+.06x} (2 MUFU).
// blocks [4096,6144): W fp16 convert.
__global__ __launch_bounds__(256) void prep_kernel(const float* __restrict__ x,
                                                   const float* __restrict__ C) {
    if (blockIdx.x < 4096) {
        int idx = blockIdx.x * 256 + threadIdx.x;    // b*256 + i
        float xv = x[idx];
        float e  = __expf(0.02f * xv);
        float r  = __fdividef(1.0f, e);
        float e2 = e * e,  e3 = e2 * e,  e5 = e2 * e3;
        float r2 = r * r,  r3 = r2 * r,  r5 = r2 * r3;
        g_P[idx] = make_float4(r5, r3, e5, e3);   // {start-, step-, start+, step+}
    } else {
        int t = (blockIdx.x - 4096) * 256 + threadIdx.x;
        size_t lin = (size_t)t * 4;
        int s  = (int)(lin >> 20);
        int o  = (int)((lin >> 12) & 255);
        int kp = (int)(lin & 4095);
        float4 v = *reinterpret_cast<const float4*>(C + lin);
        uint32_t h0 = packh(__float2half_rn(v.x), __float2half_rn(v.y));
        uint32_t h1 = packh(__float2half_rn(v.z), __float2half_rn(v.w));
        size_t op = (size_t)o * Kz + (size_t)s * 4096 + kp;
        *reinterpret_cast<uint2*>(g_W + op) = make_uint2(h0, h1);
    }
}

// -------------------------------- warp-specialized split-K mma.sync GEMM --
// g_part[z][B][O] = A[:, z*4096:(z+1)*4096] * W^T ; A generated on the fly.
// Block: 320 threads = 8 consumer warps (64x128 tile) + 2 producer warps.
// Producers: P register-prefetched one chunk ahead; dual step^2 chains.
#define BM 64
#define BN 128
#define NSTG 4
#define STG_BYTES 24576        // A 8K | W 16K
#define NCHUNK 64              // per split: 4096 / 64
#define SMEM_SIZE (NSTG * STG_BYTES + 1024)

// swizzled within-tile byte offset for (row, 16B-chunk ck), 128B rows
#define SWADDR(row, ck) ((uint32_t)((row) * 128 + (((ck) ^ ((row) & 7)) << 4)))

__device__ __forceinline__ void load_W(uint32_t orig, int st, int c,
                                       int t, int n0, size_t kbase) {
    uint32_t sb = orig + st * STG_BYTES;
    size_t ko = kbase + (size_t)c * 64;
#pragma unroll
    for (int j = 0; j < 4; j++) {          // 128 rows x 8 chunks = 1024 cp16
        int idx = t + j * 256;
        int row = idx >> 3, ck = idx & 7;
        cp16(sb + 8192 + SWADDR(row, ck), g_W + (size_t)(n0 + row) * Kz + ko + ck * 8);
    }
}

// producer: generate row p of A tile for one chunk from REGISTER P values.
// dual chains with step^2: even g from a, odd g from b.
__device__ __forceinline__ void gen_A_reg(uint32_t orig, int st, int p,
                                          const float4* Pr, int s) {
    uint32_t sb = orig + st * STG_BYTES;
#pragma unroll
    for (int il = 0; il < 4; il++) {
        float4 P = Pr[il];
        float f    = s ? P.z : P.x;        // e^{±0.10 x}
        float stp  = s ? P.w : P.y;        // e^{±0.06 x}
        float s2   = stp * stp;
        float a = f, b = f * stp;          // even / odd g chains
        uint32_t h[8];
#pragma unroll
        for (int j = 0; j < 8; j++) {
            __half2 hp = __floats2half2_rn(a, b);
            h[j] = *reinterpret_cast<uint32_t*>(&hp);
            a *= s2; b *= s2;
        }
        uint32_t a0 = sb + SWADDR(p, il * 2);
        uint32_t a1 = sb + SWADDR(p, il * 2 + 1);
        asm volatile("st.shared.v4.b32 [%0], {%1,%2,%3,%4};"
                     :: "r"(a0), "r"(h[0]), "r"(h[1]), "r"(h[2]), "r"(h[3]) : "memory");
        asm volatile("st.shared.v4.b32 [%0], {%1,%2,%3,%4};"
                     :: "r"(a1), "r"(h[4]), "r"(h[5]), "r"(h[6]), "r"(h[7]) : "memory");
    }
}

__global__ __launch_bounds__(320, 2) void gemm_kernel() {
    extern __shared__ unsigned char smem_raw[];
    uint32_t orig = (smem_u32(smem_raw) + 1023u) & ~1023u;

    int t    = threadIdx.x;
    int lane = t & 31;
    int wid  = t >> 5;
    int m0   = blockIdx.y * BM;
    int n0   = blockIdx.x * BN;
    int z    = blockIdx.z;
    size_t kbase = (size_t)z * 4096;

    if (t < 256) {
        // ============================ consumers ============================
        int wm = wid & 1;            // 0..1 -> 32-row band
        int wn = wid >> 1;           // 0..3 -> 32-col band

        float acc[2][4][4];
#pragma unroll
        for (int mt = 0; mt < 2; mt++)
#pragma unroll
            for (int nt = 0; nt < 4; nt++)
#pragma unroll
                for (int r = 0; r < 4; r++) acc[mt][nt][r] = 0.0f;

        int a_row_base = wm * 32 + (lane & 15);                 // + mt*16
        int a_ckx      = lane >> 4;
        int b_n_off    = ((lane >> 4) & 1) * 8 + (lane & 7);    // + wn*32 + q*16
        int b_ckx      = (lane >> 3) & 1;

        load_W(orig, 0, 0, t, n0, kbase); cp_commit();
        load_W(orig, 1, 1, t, n0, kbase); cp_commit();
        load_W(orig, 2, 2, t, n0, kbase); cp_commit();

        for (int c = 0; c < NCHUNK; c++) {
            cp_wait2();
            __syncthreads();   // A(stage c) from producers + W(stage c) ready

            if (c + 3 < NCHUNK) load_W(orig, (c + 3) & 3, c + 3, t, n0, kbase);
            cp_commit();

            uint32_t sb = orig + (c & 3) * STG_BYTES;
#pragma unroll
            for (int ks = 0; ks < 4; ks++) {
                uint32_t av[2][4], bv[2][4];
#pragma unroll
                for (int mt = 0; mt < 2; mt++)
                    ldsm4(av[mt], sb + SWADDR(a_row_base + mt * 16, ks * 2 + a_ckx));
#pragma unroll
                for (int q = 0; q < 2; q++) {
                    int n = wn * 32 + q * 16 + b_n_off;
                    ldsm4(bv[q], sb + 8192 + SWADDR(n, ks * 2 + b_ckx));
                }
#pragma unroll
                for (int mt = 0; mt < 2; mt++)
#pragma unroll
                    for (int nt = 0; nt < 4; nt++) {
                        int q = nt >> 1, pr = (nt & 1) * 2;
                        mma16816(acc[mt][nt], av[mt], &bv[q][pr]);
                    }
            }
        }

        // epilogue: store partials
        float* pout = g_part[z];
#pragma unroll
        for (int mt = 0; mt < 2; mt++) {
            int row = m0 + wm * 32 + mt * 16 + (lane >> 2);
#pragma unroll
            for (int nt = 0; nt < 4; nt++) {
                int col = n0 + wn * 32 + nt * 8 + (lane & 3) * 2;
                float2 r0, r1;
                r0.x = acc[mt][nt][0];
                r0.y = acc[mt][nt][1];
                r1.x = acc[mt][nt][2];
                r1.y = acc[mt][nt][3];
                *reinterpret_cast<float2*>(pout + (size_t)row * Oz + col) = r0;
                *reinterpret_cast<float2*>(pout + (size_t)(row + 8) * Oz + col) = r1;
            }
        }
    } else {
        // ============================ producers ============================
        int p = t - 256;                                   // 0..63 = A tile row
        const float4* Prow = g_P + (size_t)(m0 + p) * Iz;  // this row's P table

        float4 Pr[4];
        // prologue: gen stages 0..2 directly, then prefetch chunk 3 into regs
#pragma unroll
        for (int c0 = 0; c0 < 3; c0++) {
#pragma unroll
            for (int il = 0; il < 4; il++) Pr[il] = __ldg(Prow + c0 * 4 + il);
            gen_A_reg(orig, c0, p, Pr, z);
        }
#pragma unroll
        for (int il = 0; il < 4; il++) Pr[il] = __ldg(Prow + 3 * 4 + il);

        for (int c = 0; c < NCHUNK; c++) {
            __syncthreads();
            // generate stage c+3 from prefetched regs (pure ALU+STS: short)
            if (c + 3 < NCHUNK) gen_A_reg(orig, (c + 3) & 3, p, Pr, z);
            // prefetch P for chunk c+4 (latency spans the whole next chunk)
            if (c + 4 < NCHUNK) {
#pragma unroll
                for (int il = 0; il < 4; il++)
                    Pr[il] = __ldg(Prow + (c + 4) * 4 + il);
            }
        }
    }
}

// ------------------------------------------------------------ reduce ------
// out = part0 + part1 + bias
__global__ __launch_bounds__(256) void reduce_kernel(const float* __restrict__ bias,
                                                     float* __restrict__ out) {
    size_t lin = ((size_t)blockIdx.x * 256 + threadIdx.x) * 4;
    int col = (int)(lin & 255);
    float4 p0 = *reinterpret_cast<const float4*>(&g_part[0][lin]);
    float4 p1 = *reinterpret_cast<const float4*>(&g_part[1][lin]);
    float4 bv = *reinterpret_cast<const float4*>(bias + col);
    float4 r;
    r.x = p0.x + p1.x + bv.x;
    r.y = p0.y + p1.y + bv.y;
    r.z = p0.z + p1.z + bv.z;
    r.w = p0.w + p1.w + bv.w;
    *reinterpret_cast<float4*>(out + lin) = r;
}

// -------------------------------------------------------------- launcher --
extern "C" void kernel_launch(void* const* d_in, const int* in_sizes, int n_in,
                              void* d_out, int out_size) {
    const float* x    = (const float*)d_in[0];
    const float* coef = (const float*)d_in[1];
    const float* bias = (const float*)d_in[2];
    float* out = (float*)d_out;

    static int configured = 0;
    if (!configured) {
        cudaFuncSetAttribute(gemm_kernel,
                             cudaFuncAttributeMaxDynamicSharedMemorySize, SMEM_SIZE);
        configured = 1;
    }

    prep_kernel<<<4096 + 2048, 256>>>(x, coef);
    dim3 grid(Oz / BN, Bz / BM, 2);   // (2, 64, 2) = 256 CTAs
    gemm_kernel<<<grid, 320, SMEM_SIZE>>>();
    reduce_kernel<<<(Bz * Oz) / 1024, 256>>>(bias, out);
}

// round 13
// speedup vs baseline: 1.0731x; 1.0731x over previous
#include <cuda_runtime.h>
#include <cuda_fp16.h>
#include <cstdint>

// Problem dims
#define Bz 4096
#define Iz 256
#define Oz 256
#define Kz 8192   // 2 * Iz * 16 ; k = s*4096 + i*16 + g

// Scratch globals (no allocs allowed)
__device__ __half g_A[(size_t)Bz * Kz];        // features fp16 (64 MB)
__device__ __half g_W[(size_t)Oz * Kz];        // weights  fp16 (4 MB)
__device__ float  g_part[2][(size_t)Bz * Oz];  // split-K partials (8 MB)

// ---------------------------------------------------------------- helpers --
__device__ __forceinline__ uint32_t smem_u32(const void* p) {
    uint32_t a;
    asm("{ .reg .u64 t; cvta.to.shared.u64 t, %1; cvt.u32.u64 %0, t; }"
        : "=r"(a) : "l"(p));
    return a;
}
__device__ __forceinline__ void cp16(uint32_t dst, const void* src) {
    asm volatile("cp.async.cg.shared.global [%0], [%1], 16;" :: "r"(dst), "l"(src) : "memory");
}
__device__ __forceinline__ void cp_commit() {
    asm volatile("cp.async.commit_group;" ::: "memory");
}
__device__ __forceinline__ void cp_wait2() {
    asm volatile("cp.async.wait_group 2;" ::: "memory");
}
__device__ __forceinline__ void ldsm4(uint32_t* r, uint32_t a) {
    asm volatile("ldmatrix.sync.aligned.m8n8.x4.shared.b16 {%0,%1,%2,%3}, [%4];"
                 : "=r"(r[0]), "=r"(r[1]), "=r"(r[2]), "=r"(r[3]) : "r"(a));
}
__device__ __forceinline__ void mma16816(float* d, const uint32_t* a, const uint32_t* b) {
    asm volatile(
        "mma.sync.aligned.m16n8k16.row.col.f32.f16.f16.f32 "
        "{%0,%1,%2,%3}, {%4,%5,%6,%7}, {%8,%9}, {%0,%1,%2,%3};"
        : "+f"(d[0]), "+f"(d[1]), "+f"(d[2]), "+f"(d[3])
        : "r"(a[0]), "r"(a[1]), "r"(a[2]), "r"(a[3]), "r"(b[0]), "r"(b[1]));
}
__device__ __forceinline__ uint32_t packh(__half a, __half b) {
    return ((uint32_t)__half_as_ushort(b) << 16) | __half_as_ushort(a);
}

// ------------------------------------------------------- merged pre-pass --
// blocks [0,4096): features (2 MUFU per thread) -> g_A.
// blocks [4096,6144): W fp16 convert.
__global__ __launch_bounds__(256) void prep_kernel(const float* __restrict__ x,
                                                   const float* __restrict__ C) {
    if (blockIdx.x < 4096) {
        int idx = blockIdx.x * 256 + threadIdx.x;    // b*256 + i
        float xv = x[idx];

        float e  = __expf(0.02f * xv);
        float r  = __fdividef(1.0f, e);
        float e2 = e * e,  e3 = e2 * e,  e5 = e2 * e3;
        float r2 = r * r,  r3 = r2 * r,  r5 = r2 * r3;
        float tn = r3, tp = e3;      // steps  e^{∓0.06x}
        float fn = r5, fp = e5;      // starts e^{∓0.10x}

        uint32_t nw[8], pw[8];
#pragma unroll
        for (int q = 0; q < 8; q++) {
            __half n0 = __float2half_rn(fn); fn *= tn;
            __half n1 = __float2half_rn(fn); fn *= tn;
            nw[q] = packh(n0, n1);
            __half p0 = __float2half_rn(fp); fp *= tp;
            __half p1 = __float2half_rn(fp); fp *= tp;
            pw[q] = packh(p0, p1);
        }

        size_t base = ((size_t)(idx >> 8)) * Kz + (size_t)(idx & 255) * 16;
        uint4* dn = reinterpret_cast<uint4*>(g_A + base);          // s=0
        uint4* dp = reinterpret_cast<uint4*>(g_A + base + 4096);   // s=1
        dn[0] = make_uint4(nw[0], nw[1], nw[2], nw[3]);
        dn[1] = make_uint4(nw[4], nw[5], nw[6], nw[7]);
        dp[0] = make_uint4(pw[0], pw[1], pw[2], pw[3]);
        dp[1] = make_uint4(pw[4], pw[5], pw[6], pw[7]);
    } else {
        int t = (blockIdx.x - 4096) * 256 + threadIdx.x;
        size_t lin = (size_t)t * 4;
        int s  = (int)(lin >> 20);
        int o  = (int)((lin >> 12) & 255);
        int kp = (int)(lin & 4095);
        float4 v = *reinterpret_cast<const float4*>(C + lin);
        uint32_t h0 = packh(__float2half_rn(v.x), __float2half_rn(v.y));
        uint32_t h1 = packh(__float2half_rn(v.z), __float2half_rn(v.w));
        size_t op = (size_t)o * Kz + (size_t)s * 4096 + kp;
        *reinterpret_cast<uint2*>(g_W + op) = make_uint2(h0, h1);
    }
}

// ------------------------------------------------- split-K mma.sync GEMM --
// g_part[z][B][O] = A[:, z*4096:(z+1)*4096] * W^T  (fp32 accum)
// CTA tile 128x128, K-chunk 64, 4-stage ring, 8 warps of 32x64.
// grid (Oz/128=2, Bz/128=32, 2) = 128 CTAs, 1/SM, one wave.
#define BM 128
#define BN 128
#define NSTG 4
#define STG_BYTES 32768        // A 16K | W 16K
#define NCHUNK 64              // per split: 4096 / 64  (R12 bug: was 32)
#define SMEM_SIZE (NSTG * STG_BYTES + 1024)

// swizzled within-tile byte offset for (row, 16B-chunk ck), 128B rows
#define SWADDR(row, ck) ((uint32_t)((row) * 128 + (((ck) ^ ((row) & 7)) << 4)))

__device__ __forceinline__ void load_stage(uint32_t orig, int st, int c,
                                           int t, int m0, int n0, size_t kbase) {
    uint32_t sb = orig + st * STG_BYTES;
    size_t ko = kbase + (size_t)c * 64;
#pragma unroll
    for (int j = 0; j < 4; j++) {          // A: 128 rows x 8 chunks = 1024
        int idx = t + j * 256;
        int row = idx >> 3, ck = idx & 7;
        cp16(sb + SWADDR(row, ck), g_A + (size_t)(m0 + row) * Kz + ko + ck * 8);
    }
#pragma unroll
    for (int j = 0; j < 4; j++) {          // W: 128 rows x 8 chunks = 1024
        int idx = t + j * 256;
        int row = idx >> 3, ck = idx & 7;
        cp16(sb + 16384 + SWADDR(row, ck), g_W + (size_t)(n0 + row) * Kz + ko + ck * 8);
    }
}

__global__ __launch_bounds__(256, 1) void gemm_kernel() {
    extern __shared__ unsigned char smem_raw[];
    uint32_t orig = (smem_u32(smem_raw) + 1023u) & ~1023u;

    int t    = threadIdx.x;
    int lane = t & 31;
    int wid  = t >> 5;
    int wm   = wid >> 1;         // 0..3 -> 32-row band
    int wn   = wid & 1;          // 0..1 -> 64-col band
    int m0   = blockIdx.y * BM;
    int n0   = blockIdx.x * BN;
    int z    = blockIdx.z;
    size_t kbase = (size_t)z * 4096;

    float acc[2][8][4];
#pragma unroll
    for (int mt = 0; mt < 2; mt++)
#pragma unroll
        for (int nt = 0; nt < 8; nt++)
#pragma unroll
            for (int r = 0; r < 4; r++) acc[mt][nt][r] = 0.0f;

    // per-lane ldmatrix address components
    int a_row_base = wm * 32 + (lane & 15);                 // + mt*16
    int a_ckx      = lane >> 4;                             // k-half select
    int b_n_off    = ((lane >> 4) & 1) * 8 + (lane & 7);    // + wn*64 + q*16
    int b_ckx      = (lane >> 3) & 1;

    // prologue: 3 stages in flight
    load_stage(orig, 0, 0, t, m0, n0, kbase); cp_commit();
    load_stage(orig, 1, 1, t, m0, n0, kbase); cp_commit();
    load_stage(orig, 2, 2, t, m0, n0, kbase); cp_commit();

    for (int c = 0; c < NCHUNK; c++) {
        cp_wait2();
        __syncthreads();   // single barrier per chunk (orders stage reuse too)

        if (c + 3 < NCHUNK) load_stage(orig, (c + 3) & 3, c + 3, t, m0, n0, kbase);
        cp_commit();

        uint32_t sb = orig + (c & 3) * STG_BYTES;
#pragma unroll
        for (int ks = 0; ks < 4; ks++) {
            uint32_t av[2][4], bv[4][4];
#pragma unroll
            for (int mt = 0; mt < 2; mt++)
                ldsm4(av[mt], sb + SWADDR(a_row_base + mt * 16, ks * 2 + a_ckx));
#pragma unroll
            for (int q = 0; q < 4; q++) {
                int n = wn * 64 + q * 16 + b_n_off;
                ldsm4(bv[q], sb + 16384 + SWADDR(n, ks * 2 + b_ckx));
            }
#pragma unroll
            for (int mt = 0; mt < 2; mt++)
#pragma unroll
                for (int nt = 0; nt < 8; nt++) {
                    int q = nt >> 1, pr = (nt & 1) * 2;
                    mma16816(acc[mt][nt], av[mt], &bv[q][pr]);
                }
        }
    }

    // epilogue: store partials (fragment layout of m16n8 f32 d-regs)
    float* pout = g_part[z];
#pragma unroll
    for (int mt = 0; mt < 2; mt++) {
        int row = m0 + wm * 32 + mt * 16 + (lane >> 2);
#pragma unroll
        for (int nt = 0; nt < 8; nt++) {
            int col = n0 + wn * 64 + nt * 8 + (lane & 3) * 2;
            float2 r0, r1;
            r0.x = acc[mt][nt][0];
            r0.y = acc[mt][nt][1];
            r1.x = acc[mt][nt][2];
            r1.y = acc[mt][nt][3];
            *reinterpret_cast<float2*>(pout + (size_t)row * Oz + col) = r0;
            *reinterpret_cast<float2*>(pout + (size_t)(row + 8) * Oz + col) = r1;
        }
    }
}

// ------------------------------------------------------------ reduce ------
// out = part0 + part1 + bias
__global__ __launch_bounds__(256) void reduce_kernel(const float* __restrict__ bias,
                                                     float* __restrict__ out) {
    size_t lin = ((size_t)blockIdx.x * 256 + threadIdx.x) * 4;
    int col = (int)(lin & 255);
    float4 p0 = *reinterpret_cast<const float4*>(&g_part[0][lin]);
    float4 p1 = *reinterpret_cast<const float4*>(&g_part[1][lin]);
    float4 bv = *reinterpret_cast<const float4*>(bias + col);
    float4 r;
    r.x = p0.x + p1.x + bv.x;
    r.y = p0.y + p1.y + bv.y;
    r.z = p0.z + p1.z + bv.z;
    r.w = p0.w + p1.w + bv.w;
    *reinterpret_cast<float4*>(out + lin) = r;
}

// -------------------------------------------------------------- launcher --
extern "C" void kernel_launch(void* const* d_in, const int* in_sizes, int n_in,
                              void* d_out, int out_size) {
    const float* x    = (const float*)d_in[0];
    const float* coef = (const float*)d_in[1];
    const float* bias = (const float*)d_in[2];
    float* out = (float*)d_out;

    static int configured = 0;
    if (!configured) {
        cudaFuncSetAttribute(gemm_kernel,
                             cudaFuncAttributeMaxDynamicSharedMemorySize, SMEM_SIZE);
        configured = 1;
    }

    prep_kernel<<<4096 + 2048, 256>>>(x, coef);
    dim3 grid(Oz / BN, Bz / BM, 2);   // (2, 32, 2) = 128 CTAs
    gemm_kernel<<<grid, 256, SMEM_SIZE>>>();
    reduce_kernel<<<(Bz * Oz) / 1024, 256>>>(bias, out);
}